// round 15
// baseline (speedup 1.0000x reference)
#include <cuda_runtime.h>
#include <cuda_bf16.h>
#include <math.h>

// ============================================================================
// Bayesian LSTM forward:  B=8192, T=256, IN=1, H=10
// R14: ILP=2 — each lane owns one gate-row j for TWO batch elements (e, e+3).
//      6 elements per warp, 1366 one-warp blocks. Two independent dependency
//      chains per warp fill each other's stall gaps. Weights (40 regs) shared
//      between the two chains. SMEM double-buffered h broadcast (conflict-free
//      LDS.128, verified bank mapping for all 7 groups x both buffers).
// ============================================================================

#define HDIM   10
#define TSTEPS 256
#define BATCH  8192

using u64 = unsigned long long;

// ---------------- packed f32x2 helpers ----------------
__device__ __forceinline__ u64 pack2(float lo, float hi) {
    u64 r; asm("mov.b64 %0, {%1, %2};" : "=l"(r) : "f"(lo), "f"(hi)); return r;
}
__device__ __forceinline__ void unpack2(u64 v, float& lo, float& hi) {
    asm("mov.b64 {%0, %1}, %2;" : "=f"(lo), "=f"(hi) : "l"(v));
}
__device__ __forceinline__ u64 ffma2(u64 a, u64 b, u64 c) {
    u64 d; asm("fma.rn.f32x2 %0, %1, %2, %3;" : "=l"(d) : "l"(a), "l"(b), "l"(c)); return d;
}
__device__ __forceinline__ u64 fmul2(u64 a, u64 b) {
    u64 d; asm("mul.rn.f32x2 %0, %1, %2;" : "=l"(d) : "l"(a), "l"(b)); return d;
}
__device__ __forceinline__ u64 fadd2(u64 a, u64 b) {
    u64 d; asm("add.rn.f32x2 %0, %1, %2;" : "=l"(d) : "l"(a), "l"(b)); return d;
}
__device__ __forceinline__ float ex2a(float x) {
    float y; asm("ex2.approx.f32 %0, %1;" : "=f"(y) : "f"(x)); return y;
}
__device__ __forceinline__ float rcpa(float x) {
    float y; asm("rcp.approx.f32 %0, %1;" : "=f"(y) : "f"(x)); return y;
}

// ---------------- packed, prescaled sampled weights ----------------
// Per gate-row j (0..9), per hidden m (0..9):
//   g_wif[j][m] = ( K1*w_hh[m][ j],   K1*w_hh[m][10+j] )   (i,f)
//   g_wgo[j][m] = ( K2*w_hh[m][20+j], K1*w_hh[m][30+j] )   (g,o)
// K1 = -log2(e) (sigmoid), K2 = -2*log2(e) (tanh).
__device__ u64  g_wif[10][10];
__device__ u64  g_wgo[10][10];
__device__ u64  g_xif[10], g_xgo[10];
__device__ u64  g_bif[10], g_bgo[10];
__device__ float g_linw[HDIM];
__device__ float g_linb;

#define K1C (-1.44269504088896341f)
#define K2C (-2.88539008177792681f)

__global__ void sample_pack_kernel(
    const float* __restrict__ w_ih_mu, const float* __restrict__ w_ih_rho,
    const float* __restrict__ w_hh_mu, const float* __restrict__ w_hh_rho,
    const float* __restrict__ b_mu,    const float* __restrict__ b_rho,
    const float* __restrict__ eps_ih,  const float* __restrict__ eps_hh,
    const float* __restrict__ eps_b,
    const float* __restrict__ lin_w,   const float* __restrict__ lin_b)
{
    __shared__ float s_wih[40];
    __shared__ float s_b[40];
    __shared__ float s_whh[10][40];
    int t = threadIdx.x;

    for (int g = t; g < 40; g += blockDim.x) {
        s_wih[g] = w_ih_mu[g] + log1pf(expf(w_ih_rho[g])) * eps_ih[g];
        s_b[g]   = b_mu[g]    + log1pf(expf(b_rho[g]))    * eps_b[g];
    }
    for (int idx = t; idx < 400; idx += blockDim.x) {
        int m = idx / 40, g = idx % 40;
        s_whh[m][g] = w_hh_mu[idx] + log1pf(expf(w_hh_rho[idx])) * eps_hh[idx];
    }
    __syncthreads();

    for (int idx = t; idx < 100; idx += blockDim.x) {
        int j = idx / 10, m = idx % 10;
        g_wif[j][m] = pack2(K1C * s_whh[m][j],      K1C * s_whh[m][10 + j]);
        g_wgo[j][m] = pack2(K2C * s_whh[m][20 + j], K1C * s_whh[m][30 + j]);
    }
    if (t < 10) {
        int j = t;
        g_xif[j] = pack2(K1C * s_wih[j],      K1C * s_wih[10 + j]);
        g_xgo[j] = pack2(K2C * s_wih[20 + j], K1C * s_wih[30 + j]);
        g_bif[j] = pack2(K1C * s_b[j],        K1C * s_b[10 + j]);
        g_bgo[j] = pack2(K2C * s_b[20 + j],   K1C * s_b[30 + j]);
    }
    if (t < HDIM) g_linw[t] = lin_w[t];
    if (t == 0)   g_linb = lin_b[0];
}

// Fused exponent-domain pointwise (validated math, rel_err ~5e-7):
//   A=e^-zi, F=e^-zf, B=e^-2zg, C=e^-zo
//   chat' = (chat*P + K2*(1-B)*Q) * rcp(Q*P),  P=(1+A)(1+B), Q=1+F
//   D = 2^chat' = e^-2c';  h = (1-D) * rcp((1+C)(1+D))
__device__ __forceinline__ float lstm_pointwise(u64 sif, u64 sgo, float& chat) {
    float ai, af, ag, ao;
    unpack2(sif, ai, af);
    unpack2(sgo, ag, ao);
    const float A = ex2a(ai);
    const float F = ex2a(af);
    const float B = ex2a(ag);
    const float C = ex2a(ao);
    const float P  = (1.f + A) * (1.f + B);
    const float Q  = 1.f + F;
    const float kg = fmaf(B, -K2C, K2C);          // K2*(1-B)
    const float num = fmaf(chat, P, kg * Q);
    chat = num * rcpa(Q * P);
    const float D = ex2a(chat);
    return (1.f - D) * rcpa((1.f + C) * (1.f + D));
}

// ---------------- main LSTM kernel ----------------
// 32-thread blocks. Lanes [10g,10g+10) form group g (g=0,1,2); lane owns
// gate-row j = lane-10g for elements e0 = 6*blk+g and e1 = e0+3.
// SMEM groups: 0..2 for e0's, 3..5 for e1's, 6 = scratch for lanes 30,31.
// Group bases chosen so every LDS.128 (both buffers, both hp loads) is
// bank-conflict-free across the 4 concurrent group addresses.
__global__ void __launch_bounds__(32) lstm_fwd_kernel(
    const float* __restrict__ x, float* __restrict__ out)
{
    __shared__ __align__(16) unsigned char sh[7 * 224 + 32];

    const int lane = threadIdx.x & 31;
    const bool idle = (lane >= 30);
    const int grp  = idle ? 0 : (lane / 10);
    const int row  = idle ? (lane - 30) : (lane - grp * 10);

    int e0 = blockIdx.x * 6 + grp;
    int e1 = e0 + 3;
    const bool v0 = !idle && (e0 < BATCH);
    const bool v1 = !idle && (e1 < BATCH);
    const int ce0 = (e0 < BATCH) ? e0 : (BATCH - 1);
    const int ce1 = (e1 < BATCH) ? e1 : (BATCH - 1);

    const int sg0 = idle ? 6 : grp;
    const int sg1 = idle ? 6 : (grp + 3);
    unsigned char* const gb0 = sh + sg0 * 224 + (sg0 == 6 ? 16 : 0);
    unsigned char* const gb1 = sh + sg1 * 224 + (sg1 == 6 ? 16 : 0);
    // bufA = gb + 0, bufB = gb + 96

    // ---- weights into registers (shared by both chains) ----
    u64 wif[10], wgo[10];
#pragma unroll
    for (int m = 0; m < 10; m++) {
        wif[m] = g_wif[row][m];
        wgo[m] = g_wgo[row][m];
    }
    const u64 xif = g_xif[row], xgo = g_xgo[row];
    const u64 bif = g_bif[row], bgo = g_bgo[row];

    float chat0 = 0.f, chat1 = 0.f;

    // prefill parity-0 buffers with h = 0 pairs
    *reinterpret_cast<u64*>(gb0 + 8 * row) = 0ull;
    *reinterpret_cast<u64*>(gb1 + 8 * row) = 0ull;
    __syncwarp();

    const float4* xp0 = reinterpret_cast<const float4*>(x + (size_t)ce0 * TSTEPS);
    const float4* xp1 = reinterpret_cast<const float4*>(x + (size_t)ce1 * TSTEPS);

#pragma unroll 1
    for (int t4 = 0; t4 < TSTEPS / 4; t4++) {
        const float4 xa = xp0[t4];
        const float4 xb = xp1[t4];
        const float xs0[4] = {xa.x, xa.y, xa.z, xa.w};
        const float xs1[4] = {xb.x, xb.y, xb.z, xb.w};
#pragma unroll
        for (int s = 0; s < 4; s++) {
            const int roff = (s & 1) ? 96 : 0;
            const int woff = 96 - roff;
            unsigned char* const rb0 = gb0 + roff;
            unsigned char* const wb0 = gb0 + woff;
            unsigned char* const rb1 = gb1 + roff;
            unsigned char* const wb1 = gb1 + woff;

            // ---- both matvecs, streaming LDS.128 h-pairs, tree-split ----
            const u64 xpk0 = pack2(xs0[s], xs0[s]);
            const u64 xpk1 = pack2(xs1[s], xs1[s]);
            u64 a0if = ffma2(xpk0, xif, bif);
            u64 a0go = ffma2(xpk0, xgo, bgo);
            u64 b0if = ffma2(xpk1, xif, bif);
            u64 b0go = ffma2(xpk1, xgo, bgo);
            u64 a1if, a1go, b1if, b1go;
            {
                const ulonglong2 ha = *reinterpret_cast<const ulonglong2*>(rb0);
                const ulonglong2 hb = *reinterpret_cast<const ulonglong2*>(rb1);
                a1if = fmul2(ha.x, wif[0]);  a1go = fmul2(ha.x, wgo[0]);
                a0if = ffma2(ha.y, wif[1], a0if);  a0go = ffma2(ha.y, wgo[1], a0go);
                b1if = fmul2(hb.x, wif[0]);  b1go = fmul2(hb.x, wgo[0]);
                b0if = ffma2(hb.y, wif[1], b0if);  b0go = ffma2(hb.y, wgo[1], b0go);
            }
#pragma unroll
            for (int q = 1; q < 5; q++) {
                const int m0 = 2 * q, m1 = 2 * q + 1;
                const ulonglong2 ha = *reinterpret_cast<const ulonglong2*>(rb0 + 16 * q);
                const ulonglong2 hb = *reinterpret_cast<const ulonglong2*>(rb1 + 16 * q);
                a1if = ffma2(ha.x, wif[m0], a1if);  a1go = ffma2(ha.x, wgo[m0], a1go);
                a0if = ffma2(ha.y, wif[m1], a0if);  a0go = ffma2(ha.y, wgo[m1], a0go);
                b1if = ffma2(hb.x, wif[m0], b1if);  b1go = ffma2(hb.x, wgo[m0], b1go);
                b0if = ffma2(hb.y, wif[m1], b0if);  b0go = ffma2(hb.y, wgo[m1], b0go);
            }

            // ---- pointwise, both chains (ptxas interleaves) ----
            const float h0 = lstm_pointwise(fadd2(a0if, a1if), fadd2(a0go, a1go), chat0);
            const float h1 = lstm_pointwise(fadd2(b0if, b1if), fadd2(b0go, b1go), chat1);

            // ---- publish duplicated pairs, one warp sync ----
            *reinterpret_cast<u64*>(wb0 + 8 * row) = pack2(h0, h0);
            *reinterpret_cast<u64*>(wb1 + 8 * row) = pack2(h1, h1);
            __syncwarp();
        }
    }

    // 256 steps: last write (s=3) went to parity-0 buffer (bufA = gb + 0).
    if (row == 0 && !idle) {
        if (v0) {
            float acc = g_linb;
#pragma unroll
            for (int m = 0; m < 10; m++) {
                const float hm = *reinterpret_cast<const float*>(gb0 + 8 * m);
                acc = fmaf(hm, g_linw[m], acc);
            }
            out[e0] = acc;
        }
        if (v1) {
            float acc = g_linb;
#pragma unroll
            for (int m = 0; m < 10; m++) {
                const float hm = *reinterpret_cast<const float*>(gb1 + 8 * m);
                acc = fmaf(hm, g_linw[m], acc);
            }
            out[e1] = acc;
        }
    }
}

// ---------------- launch ----------------
extern "C" void kernel_launch(void* const* d_in, const int* in_sizes, int n_in,
                              void* d_out, int out_size)
{
    const float* x        = (const float*)d_in[0];
    const float* w_ih_mu  = (const float*)d_in[1];
    const float* w_ih_rho = (const float*)d_in[2];
    const float* w_hh_mu  = (const float*)d_in[3];
    const float* w_hh_rho = (const float*)d_in[4];
    const float* b_mu     = (const float*)d_in[5];
    const float* b_rho    = (const float*)d_in[6];
    const float* eps_ih   = (const float*)d_in[7];
    const float* eps_hh   = (const float*)d_in[8];
    const float* eps_b    = (const float*)d_in[9];
    const float* lin_w    = (const float*)d_in[10];
    const float* lin_b    = (const float*)d_in[11];
    float* out = (float*)d_out;

    sample_pack_kernel<<<1, 128>>>(w_ih_mu, w_ih_rho, w_hh_mu, w_hh_rho,
                                   b_mu, b_rho, eps_ih, eps_hh, eps_b,
                                   lin_w, lin_b);

    const int nblocks = (BATCH + 5) / 6;   // 1366 one-warp blocks, 6 elems each
    lstm_fwd_kernel<<<nblocks, 32>>>(x, out);
}

// round 16
// speedup vs baseline: 1.0803x; 1.0803x over previous
#include <cuda_runtime.h>
#include <cuda_bf16.h>
#include <math.h>

// ============================================================================
// Bayesian LSTM forward:  B=8192, T=256, IN=1, H=10
// R16: m-pair f32x2 matvec. The packed operand is (h_{2q}, h_{2q+1}) — no
//      duplicated (h,h) pairs, so no unavoidable pack-MOVs. Each of the 4
//      gates gets its own f32x2 accumulator (lo = even m, hi = odd m), seeded
//      with the bias pair; horizontal finish = 1 FADD + 1 FFMA(x) per gate.
//      Broadcast stays SHFL (R9-style, measured best). 3 elems/warp, 2731
//      one-warp blocks. Exponent-domain pointwise identical to R9 (5e-7).
// ============================================================================

#define HDIM   10
#define TSTEPS 256
#define BATCH  8192

using u64 = unsigned long long;

// ---------------- packed f32x2 helpers ----------------
__device__ __forceinline__ u64 pack2(float lo, float hi) {
    u64 r; asm("mov.b64 %0, {%1, %2};" : "=l"(r) : "f"(lo), "f"(hi)); return r;
}
__device__ __forceinline__ void unpack2(u64 v, float& lo, float& hi) {
    asm("mov.b64 {%0, %1}, %2;" : "=f"(lo), "=f"(hi) : "l"(v));
}
__device__ __forceinline__ u64 ffma2(u64 a, u64 b, u64 c) {
    u64 d; asm("fma.rn.f32x2 %0, %1, %2, %3;" : "=l"(d) : "l"(a), "l"(b), "l"(c)); return d;
}
__device__ __forceinline__ float ex2a(float x) {
    float y; asm("ex2.approx.f32 %0, %1;" : "=f"(y) : "f"(x)); return y;
}
__device__ __forceinline__ float rcpa(float x) {
    float y; asm("rcp.approx.f32 %0, %1;" : "=f"(y) : "f"(x)); return y;
}

// ---------------- packed, prescaled sampled weights ----------------
// m-pair layout: per gate-row j (0..9), per m-pair q (0..4):
//   g_wI[j][q] = ( K1*w_hh[2q][j],    K1*w_hh[2q+1][j]    )
//   g_wF[j][q] = ( K1*w_hh[2q][10+j], K1*w_hh[2q+1][10+j] )
//   g_wG[j][q] = ( K2*w_hh[2q][20+j], K2*w_hh[2q+1][20+j] )
//   g_wO[j][q] = ( K1*w_hh[2q][30+j], K1*w_hh[2q+1][30+j] )
// Bias seeds: g_bI[j] = (K1*b[j], 0), etc.  x weights: scalars.
// K1 = -log2(e) (sigmoid), K2 = -2*log2(e) (tanh).
__device__ u64  g_wI[10][5], g_wF[10][5], g_wG[10][5], g_wO[10][5];
__device__ u64  g_bI[10], g_bF[10], g_bG[10], g_bO[10];
__device__ float g_xI[10], g_xF[10], g_xG[10], g_xO[10];
__device__ float g_linw[HDIM];
__device__ float g_linb;

#define K1C (-1.44269504088896341f)
#define K2C (-2.88539008177792681f)

__global__ void sample_pack_kernel(
    const float* __restrict__ w_ih_mu, const float* __restrict__ w_ih_rho,
    const float* __restrict__ w_hh_mu, const float* __restrict__ w_hh_rho,
    const float* __restrict__ b_mu,    const float* __restrict__ b_rho,
    const float* __restrict__ eps_ih,  const float* __restrict__ eps_hh,
    const float* __restrict__ eps_b,
    const float* __restrict__ lin_w,   const float* __restrict__ lin_b)
{
    __shared__ float s_wih[40];
    __shared__ float s_b[40];
    __shared__ float s_whh[10][40];
    int t = threadIdx.x;

    for (int g = t; g < 40; g += blockDim.x) {
        s_wih[g] = w_ih_mu[g] + log1pf(expf(w_ih_rho[g])) * eps_ih[g];
        s_b[g]   = b_mu[g]    + log1pf(expf(b_rho[g]))    * eps_b[g];
    }
    for (int idx = t; idx < 400; idx += blockDim.x) {
        int m = idx / 40, g = idx % 40;
        s_whh[m][g] = w_hh_mu[idx] + log1pf(expf(w_hh_rho[idx])) * eps_hh[idx];
    }
    __syncthreads();

    // recurrent weights: 50 (j,q) cells, 4 gates each
    for (int idx = t; idx < 50; idx += blockDim.x) {
        int j = idx / 5, q = idx % 5;
        int m0 = 2 * q, m1 = 2 * q + 1;
        g_wI[j][q] = pack2(K1C * s_whh[m0][j],      K1C * s_whh[m1][j]);
        g_wF[j][q] = pack2(K1C * s_whh[m0][10 + j], K1C * s_whh[m1][10 + j]);
        g_wG[j][q] = pack2(K2C * s_whh[m0][20 + j], K2C * s_whh[m1][20 + j]);
        g_wO[j][q] = pack2(K1C * s_whh[m0][30 + j], K1C * s_whh[m1][30 + j]);
    }
    if (t < 10) {
        int j = t;
        g_bI[j] = pack2(K1C * s_b[j],      0.f);
        g_bF[j] = pack2(K1C * s_b[10 + j], 0.f);
        g_bG[j] = pack2(K2C * s_b[20 + j], 0.f);
        g_bO[j] = pack2(K1C * s_b[30 + j], 0.f);
        g_xI[j] = K1C * s_wih[j];
        g_xF[j] = K1C * s_wih[10 + j];
        g_xG[j] = K2C * s_wih[20 + j];
        g_xO[j] = K1C * s_wih[30 + j];
    }
    if (t < HDIM) g_linw[t] = lin_w[t];
    if (t == 0)   g_linb = lin_b[0];
}

// ---------------- main LSTM kernel ----------------
// 32-thread blocks; lanes [10g, 10g+10) handle batch element blockIdx.x*3+g.
// Each lane owns one gate-row j; shuffles broadcast the 10 h values; matvec
// consumes them as 5 (h_{2q}, h_{2q+1}) pairs — no duplication MOVs.
__global__ void __launch_bounds__(32) lstm_fwd_kernel(
    const float* __restrict__ x, float* __restrict__ out)
{
    const int lane = threadIdx.x & 31;
    int grp  = lane / 10;                 // 0,1,2 real; 3 = idle lanes 30,31
    const bool idle = (grp >= 3);
    if (idle) grp = 2;
    const int row  = idle ? 0 : (lane - grp * 10);
    const int gbase = grp * 10;

    int elem = blockIdx.x * 3 + grp;
    const bool valid = !idle && (elem < BATCH);
    if (elem >= BATCH) elem = BATCH - 1;  // clamp for safe loads

    // ---- weights into registers (20 u64 + 4 u64 bias + 4 scalars) ----
    u64 wI[5], wF[5], wG[5], wO[5];
#pragma unroll
    for (int q = 0; q < 5; q++) {
        wI[q] = g_wI[row][q];
        wF[q] = g_wF[row][q];
        wG[q] = g_wG[row][q];
        wO[q] = g_wO[row][q];
    }
    const u64 bI = g_bI[row], bF = g_bF[row], bG = g_bG[row], bO = g_bO[row];
    const float xI = g_xI[row], xF = g_xF[row], xG = g_xG[row], xO = g_xO[row];

    float h_all[10];
#pragma unroll
    for (int m = 0; m < 10; m++) h_all[m] = 0.f;
    u64 hp[5];
#pragma unroll
    for (int q = 0; q < 5; q++) hp[q] = 0ull;

    float chat = 0.f;                     // chat = K2 * c (exponent-domain cell)
    float hown = 0.f;

    const float4* xp = reinterpret_cast<const float4*>(x + (size_t)elem * TSTEPS);

#pragma unroll 1
    for (int t4 = 0; t4 < TSTEPS / 4; t4++) {
        float4 xv = xp[t4];
        float xs[4] = {xv.x, xv.y, xv.z, xv.w};
#pragma unroll
        for (int s = 0; s < 4; s++) {
            const float xt = xs[s];

            // ---- 4 independent f32x2 gate accumulators (lo=even m, hi=odd m)
            u64 aI = ffma2(hp[0], wI[0], bI);
            u64 aF = ffma2(hp[0], wF[0], bF);
            u64 aG = ffma2(hp[0], wG[0], bG);
            u64 aO = ffma2(hp[0], wO[0], bO);
#pragma unroll
            for (int q = 1; q < 5; q++) {
                aI = ffma2(hp[q], wI[q], aI);
                aF = ffma2(hp[q], wF[q], aF);
                aG = ffma2(hp[q], wG[q], aG);
                aO = ffma2(hp[q], wO[q], aO);
            }
            // horizontal finish: lo+hi, + x*w_ih  (unpack = free reg halves)
            float lI, hI, lF, hF, lG, hG, lO, hO;
            unpack2(aI, lI, hI);
            unpack2(aF, lF, hF);
            unpack2(aG, lG, hG);
            unpack2(aO, lO, hO);
            const float ai = fmaf(xt, xI, lI) + hI;
            const float af = fmaf(xt, xF, lF) + hF;
            const float ag = fmaf(xt, xG, lG) + hG;
            const float ao = fmaf(xt, xO, lO) + hO;

            // ---- pointwise (exponent-domain, 5 ex2 + 2 rcp) ----
            // A=e^-zi, F=e^-zf, B=e^-2zg, C=e^-zo
            // chat' = (chat*P + K2*(1-B)*Q) * rcp(Q*P), P=(1+A)(1+B), Q=1+F
            // D=2^chat';  h = (1-D)*rcp((1+C)(1+D))
            const float A = ex2a(ai);
            const float F = ex2a(af);
            const float B = ex2a(ag);
            const float C = ex2a(ao);
            const float P  = (1.f + A) * (1.f + B);
            const float Q  = 1.f + F;
            const float kg = fmaf(B, -K2C, K2C);          // K2*(1-B)
            const float num = fmaf(chat, P, kg * Q);
            chat = num * rcpa(Q * P);
            const float D = ex2a(chat);
            hown = (1.f - D) * rcpa((1.f + C) * (1.f + D));

            // ---- broadcast: 10 shfl, then repack as 5 m-pairs ----
#pragma unroll
            for (int m = 0; m < 10; m++)
                h_all[m] = __shfl_sync(0xffffffffu, hown, gbase + m);
#pragma unroll
            for (int q = 0; q < 5; q++)
                hp[q] = pack2(h_all[2 * q], h_all[2 * q + 1]);
        }
    }

    if (valid && row == 0) {
        float acc = g_linb;
#pragma unroll
        for (int m = 0; m < 10; m++) acc = fmaf(h_all[m], g_linw[m], acc);
        out[elem] = acc;
    }
}

// ---------------- launch ----------------
extern "C" void kernel_launch(void* const* d_in, const int* in_sizes, int n_in,
                              void* d_out, int out_size)
{
    const float* x        = (const float*)d_in[0];
    const float* w_ih_mu  = (const float*)d_in[1];
    const float* w_ih_rho = (const float*)d_in[2];
    const float* w_hh_mu  = (const float*)d_in[3];
    const float* w_hh_rho = (const float*)d_in[4];
    const float* b_mu     = (const float*)d_in[5];
    const float* b_rho    = (const float*)d_in[6];
    const float* eps_ih   = (const float*)d_in[7];
    const float* eps_hh   = (const float*)d_in[8];
    const float* eps_b    = (const float*)d_in[9];
    const float* lin_w    = (const float*)d_in[10];
    const float* lin_b    = (const float*)d_in[11];
    float* out = (float*)d_out;

    sample_pack_kernel<<<1, 128>>>(w_ih_mu, w_ih_rho, w_hh_mu, w_hh_rho,
                                   b_mu, b_rho, eps_ih, eps_hh, eps_b,
                                   lin_w, lin_b);

    const int nblocks = (BATCH + 2) / 3;   // 2731 one-warp blocks
    lstm_fwd_kernel<<<nblocks, 32>>>(x, out);
}

// round 17
// speedup vs baseline: 1.5842x; 1.4665x over previous
#include <cuda_runtime.h>
#include <cuda_bf16.h>
#include <math.h>

// ============================================================================
// Bayesian LSTM forward:  B=8192, T=256, IN=1, H=10
// R17: R9 kernel (best measured: 1 lane/gate-row, 3 elems/warp, SHFL
//      broadcast, 2731 one-warp blocks) with ONE change — the pointwise:
//        sigma(z) = 0.5 + 0.5*tanh(z/2)  via MUFU tanh.approx
//        g = tanh(zg), h = o*tanh(c)
//      MUFU per step: 7 -> 5, rcp gone, pointwise chain ~92 -> ~52 cyc.
//      Weights prescaled by 0.5 on sigmoid columns at sampling time.
//      This is a deliberate accuracy experiment: tanh.approx error is the
//      measured quantity (predicted rel_err ~1e-4..8e-4 vs 1e-3 bound).
// ============================================================================

#define HDIM   10
#define TSTEPS 256
#define BATCH  8192

using u64 = unsigned long long;

// ---------------- packed f32x2 helpers ----------------
__device__ __forceinline__ u64 pack2(float lo, float hi) {
    u64 r; asm("mov.b64 %0, {%1, %2};" : "=l"(r) : "f"(lo), "f"(hi)); return r;
}
__device__ __forceinline__ void unpack2(u64 v, float& lo, float& hi) {
    asm("mov.b64 {%0, %1}, %2;" : "=f"(lo), "=f"(hi) : "l"(v));
}
__device__ __forceinline__ u64 ffma2(u64 a, u64 b, u64 c) {
    u64 d; asm("fma.rn.f32x2 %0, %1, %2, %3;" : "=l"(d) : "l"(a), "l"(b), "l"(c)); return d;
}
__device__ __forceinline__ u64 fmul2(u64 a, u64 b) {
    u64 d; asm("mul.rn.f32x2 %0, %1, %2;" : "=l"(d) : "l"(a), "l"(b)); return d;
}
__device__ __forceinline__ u64 fadd2(u64 a, u64 b) {
    u64 d; asm("add.rn.f32x2 %0, %1, %2;" : "=l"(d) : "l"(a), "l"(b)); return d;
}
__device__ __forceinline__ float tanha(float x) {
    float y; asm("tanh.approx.f32 %0, %1;" : "=f"(y) : "f"(x)); return y;
}

// ---------------- packed, prescaled sampled weights ----------------
// Per gate-row j (0..9), per hidden m (0..9):
//   g_wif[j][m] = ( 0.5*w_hh[m][ j],   0.5*w_hh[m][10+j] )   (i,f: z/2)
//   g_wgo[j][m] = ( 1.0*w_hh[m][20+j], 0.5*w_hh[m][30+j] )   (g: z, o: z/2)
__device__ u64  g_wif[10][10];
__device__ u64  g_wgo[10][10];
__device__ u64  g_xif[10], g_xgo[10];   // w_ih
__device__ u64  g_bif[10], g_bgo[10];   // bias
__device__ float g_linw[HDIM];
__device__ float g_linb;

__global__ void sample_pack_kernel(
    const float* __restrict__ w_ih_mu, const float* __restrict__ w_ih_rho,
    const float* __restrict__ w_hh_mu, const float* __restrict__ w_hh_rho,
    const float* __restrict__ b_mu,    const float* __restrict__ b_rho,
    const float* __restrict__ eps_ih,  const float* __restrict__ eps_hh,
    const float* __restrict__ eps_b,
    const float* __restrict__ lin_w,   const float* __restrict__ lin_b)
{
    __shared__ float s_wih[40];
    __shared__ float s_b[40];
    __shared__ float s_whh[10][40];
    int t = threadIdx.x;

    for (int g = t; g < 40; g += blockDim.x) {
        s_wih[g] = w_ih_mu[g] + log1pf(expf(w_ih_rho[g])) * eps_ih[g];
        s_b[g]   = b_mu[g]    + log1pf(expf(b_rho[g]))    * eps_b[g];
    }
    for (int idx = t; idx < 400; idx += blockDim.x) {
        int m = idx / 40, g = idx % 40;
        s_whh[m][g] = w_hh_mu[idx] + log1pf(expf(w_hh_rho[idx])) * eps_hh[idx];
    }
    __syncthreads();

    // recurrent weights: 100 (j,m) cells
    for (int idx = t; idx < 100; idx += blockDim.x) {
        int j = idx / 10, m = idx % 10;
        g_wif[j][m] = pack2(0.5f * s_whh[m][j],      0.5f * s_whh[m][10 + j]);
        g_wgo[j][m] = pack2(       s_whh[m][20 + j], 0.5f * s_whh[m][30 + j]);
    }
    // input weights + bias: 10 rows
    if (t < 10) {
        int j = t;
        g_xif[j] = pack2(0.5f * s_wih[j],      0.5f * s_wih[10 + j]);
        g_xgo[j] = pack2(       s_wih[20 + j], 0.5f * s_wih[30 + j]);
        g_bif[j] = pack2(0.5f * s_b[j],        0.5f * s_b[10 + j]);
        g_bgo[j] = pack2(       s_b[20 + j],   0.5f * s_b[30 + j]);
    }
    if (t < HDIM) g_linw[t] = lin_w[t];
    if (t == 0)   g_linb = lin_b[0];
}

// ---------------- main LSTM kernel ----------------
// 32-thread blocks; lanes [10g, 10g+10) handle batch element blockIdx.x*3+g.
// Each lane owns ONE gate-row j: computes i,f,g,o for j, updates c[j], h[j],
// then the 10-lane group broadcasts h via shfl.  (R9 structure, R17 pointwise.)
__global__ void __launch_bounds__(32) lstm_fwd_kernel(
    const float* __restrict__ x, float* __restrict__ out)
{
    const int lane = threadIdx.x & 31;
    int grp  = lane / 10;                 // 0,1,2 real; 3 = idle lanes 30,31
    const bool idle = (grp >= 3);
    if (idle) grp = 2;                    // harmless aliases for idle lanes
    const int row  = idle ? 0 : (lane - grp * 10);
    const int gbase = grp * 10;           // shfl source base for this element

    int elem = blockIdx.x * 3 + grp;
    const bool valid = !idle && (elem < BATCH);
    if (elem >= BATCH) elem = BATCH - 1;  // clamp for safe loads

    // ---- weights into registers (20 u64 = 40 regs) ----
    u64 wif[10], wgo[10];
#pragma unroll
    for (int m = 0; m < 10; m++) {
        wif[m] = g_wif[row][m];
        wgo[m] = g_wgo[row][m];
    }
    const u64 xif = g_xif[row], xgo = g_xgo[row];
    const u64 bif = g_bif[row], bgo = g_bgo[row];

    float h_all[10];
#pragma unroll
    for (int m = 0; m < 10; m++) h_all[m] = 0.f;
    float c    = 0.f;
    float hown = 0.f;

    const float4* xp = reinterpret_cast<const float4*>(x + (size_t)elem * TSTEPS);

#pragma unroll 1
    for (int t4 = 0; t4 < TSTEPS / 4; t4++) {
        float4 xv = xp[t4];
        float xs[4] = {xv.x, xv.y, xv.z, xv.w};
#pragma unroll
        for (int s = 0; s < 4; s++) {
            const float xt = xs[s];
            const u64 xpk = pack2(xt, xt);

            // ---- gates: tree-split packed matvec over m (R9-identical) ----
            u64 a0if = ffma2(xpk, xif, bif);
            u64 a0go = ffma2(xpk, xgo, bgo);
            u64 a1if, a1go;
            {
                const u64 hp0 = pack2(h_all[0], h_all[0]);
                a1if = fmul2(hp0, wif[0]);
                a1go = fmul2(hp0, wgo[0]);
            }
#pragma unroll
            for (int m = 1; m < 10; m++) {
                const u64 hp = pack2(h_all[m], h_all[m]);
                if (m & 1) {
                    a0if = ffma2(hp, wif[m], a0if);
                    a0go = ffma2(hp, wgo[m], a0go);
                } else {
                    a1if = ffma2(hp, wif[m], a1if);
                    a1go = ffma2(hp, wgo[m], a1go);
                }
            }

            // ---- pointwise via tanh.approx (5 MUFU, no rcp) ----
            // aif = (zi/2, zf/2), ago = (zg, zo/2)
            // sigma(z) = 0.5 + 0.5*tanh(z/2); g = tanh(zg)
            // c' = f*c + i*g;  h = o * tanh(c')
            float zi2, zf2, zg, zo2;
            unpack2(fadd2(a0if, a1if), zi2, zf2);
            unpack2(fadd2(a0go, a1go), zg, zo2);
            const float ti = tanha(zi2);
            const float tf = tanha(zf2);
            const float tg = tanha(zg);
            const float to = tanha(zo2);
            const float i_ = fmaf(0.5f, ti, 0.5f);
            const float f_ = fmaf(0.5f, tf, 0.5f);
            const float o_ = fmaf(0.5f, to, 0.5f);
            c = fmaf(f_, c, i_ * tg);
            hown = o_ * tanha(c);

            // ---- broadcast the 10 h values within the 10-lane group ----
#pragma unroll
            for (int m = 0; m < 10; m++)
                h_all[m] = __shfl_sync(0xffffffffu, hown, gbase + m);
        }
    }

    if (valid && row == 0) {
        float acc = g_linb;
#pragma unroll
        for (int m = 0; m < 10; m++) acc = fmaf(h_all[m], g_linw[m], acc);
        out[elem] = acc;
    }
}

// ---------------- launch ----------------
extern "C" void kernel_launch(void* const* d_in, const int* in_sizes, int n_in,
                              void* d_out, int out_size)
{
    const float* x        = (const float*)d_in[0];
    const float* w_ih_mu  = (const float*)d_in[1];
    const float* w_ih_rho = (const float*)d_in[2];
    const float* w_hh_mu  = (const float*)d_in[3];
    const float* w_hh_rho = (const float*)d_in[4];
    const float* b_mu     = (const float*)d_in[5];
    const float* b_rho    = (const float*)d_in[6];
    const float* eps_ih   = (const float*)d_in[7];
    const float* eps_hh   = (const float*)d_in[8];
    const float* eps_b    = (const float*)d_in[9];
    const float* lin_w    = (const float*)d_in[10];
    const float* lin_b    = (const float*)d_in[11];
    float* out = (float*)d_out;

    sample_pack_kernel<<<1, 128>>>(w_ih_mu, w_ih_rho, w_hh_mu, w_hh_rho,
                                   b_mu, b_rho, eps_ih, eps_hh, eps_b,
                                   lin_w, lin_b);

    const int nblocks = (BATCH + 2) / 3;   // 2731 one-warp blocks
    lstm_fwd_kernel<<<nblocks, 32>>>(x, out);
}